// round 6
// baseline (speedup 1.0000x reference)
#include <cuda_runtime.h>
#include <cstddef>
#include <cstdint>

// ---------------- problem constants ----------------
#define TT   4
#define BB   8
#define CC   512
#define VV   1024
#define HID  2048
#define NTB  (TT*BB)              // 32
#define MAIN_ELEMS (TT*BB*CC*VV)  // 16,777,216
#define NBV  (BB*VV)              // 8192 (b,v) columns

// ---------------- scratch ----------------
__device__ float g_xt[MAIN_ELEMS];      // x transposed [tb][v][c]
__device__ float g_y [MAIN_ELEMS];      // attention output (pre-LIF) [tb][v][c]
__device__ float g_xattn[MAIN_ELEMS];   // attn block output (residual for MLP)
__device__ float g_f2[MAIN_ELEMS];      // final sum, transposed [tb][v][c]
__device__ float g_wqkv[CC*3*CC];       // [k][q512|k512|v512]
__device__ float g_wp [CC*CC];
__device__ float g_wf1[CC*HID];
__device__ float g_wf2[HID*CC];
// bitmasks: layout [col=(b*1024+v)][t][W words], W = channels/32
__device__ uint32_t g_mx [NBV*4*16];
__device__ uint32_t g_mq [NBV*4*16];
__device__ uint32_t g_mk [NBV*4*16];
__device__ uint32_t g_mv [NBV*4*16];
__device__ uint32_t g_mpr[NBV*4*16];
__device__ uint32_t g_mm1[NBV*4*16];
__device__ uint32_t g_mh [NBV*4*64];
__device__ float g_attn[128*4096];      // per (n_,b,h): 64x64 attn matrix

// mask word from 2 spike bits per thread, 16-lane groups (channels = 2*lane_in_grp + bit)
__device__ __forceinline__ void put_word2(uint32_t pr, int lane, uint32_t* dst)
{
    uint32_t gm = 0xFFFFu << (16 * (lane >> 4));
    uint32_t wd = __reduce_or_sync(gm, pr << ((lane & 15) * 2));
    if ((lane & 15) == 0) dst[lane >> 4] = wd;
}

// ---------------- 32x32 tiled transpose: out[z][c][r] = in[z][r][c] ----------------
__global__ void tkern(const float* __restrict__ in, float* __restrict__ out,
                      int R, int Cn)
{
    __shared__ float t[32][33];
    size_t bs = (size_t)R * Cn * blockIdx.z;
    int r0 = blockIdx.y * 32, c0 = blockIdx.x * 32;
    int tx = threadIdx.x, ty = threadIdx.y;
#pragma unroll
    for (int j = 0; j < 4; j++)
        t[ty + 8 * j][tx] = in[bs + (size_t)(r0 + ty + 8 * j) * Cn + c0 + tx];
    __syncthreads();
#pragma unroll
    for (int j = 0; j < 4; j++)
        out[bs + (size_t)(c0 + ty + 8 * j) * R + r0 + tx] = t[tx][ty + 8 * j];
}

// ---------------- interleaved qkv weight transpose ----------------
__global__ void qkvw_kern(const float* __restrict__ qw, const float* __restrict__ kw,
                          const float* __restrict__ vw, float* __restrict__ wqkv)
{
    __shared__ float t[32][33];
    const float* src = (blockIdx.z == 0) ? qw : (blockIdx.z == 1) ? kw : vw;
    int m0 = blockIdx.y * 32, k0 = blockIdx.x * 32;
    int tx = threadIdx.x, ty = threadIdx.y;
#pragma unroll
    for (int j = 0; j < 4; j++)
        t[ty + 8 * j][tx] = src[(size_t)(m0 + ty + 8 * j) * CC + k0 + tx];
    __syncthreads();
#pragma unroll
    for (int j = 0; j < 4; j++)
        wqkv[(size_t)(k0 + ty + 8 * j) * 1536 + blockIdx.z * 512 + m0 + tx] = t[tx][ty + 8 * j];
}

// ---------------- LIF -> bitmask (512 channels, one block per (b,v)) ----------------
__global__ __launch_bounds__(256)
void lif2mask(const float* __restrict__ src, uint32_t* __restrict__ mout, float vth)
{
    int col = blockIdx.x;
    int b = col >> 10, v = col & 1023;
    int tid = threadIdx.x, wid = tid >> 5, lane = tid & 31;
    float v0 = 0.f, v1 = 0.f;
#pragma unroll
    for (int t = 0; t < 4; t++) {
        size_t ib = ((size_t)((t * 8 + b) * 1024 + v)) * 512;
        float2 xv = *(const float2*)(src + ib + 2 * tid);
        float h0 = v0 + (xv.x - v0) * 0.5f, h1 = v1 + (xv.y - v1) * 0.5f;
        uint32_t s0 = (h0 >= vth), s1 = (h1 >= vth);
        v0 = s0 ? 0.f : h0; v1 = s1 ? 0.f : h1;
        put_word2(s0 | (s1 << 1), lane, mout + ((size_t)col * 4 + t) * 16 + 2 * wid);
    }
}

// ---------------- staged sparse GEMM + fused BN/LIF ----------------
// grid: (128 col-blocks, MTOT/64 m-blocks). 256 threads = 8 warps.
// Block: 64 (b,v) columns x 64 m-channels x all 4 t. Warp owns 8 columns.
// K staged in smem 128-row tiles; warp-uniform mask walk (no divergence).
// EPI: 0=qkv(3 outputs + v float), 1=proj(+res,+fout,+mask), 2=fc1(mask), 3=fc2(+res,fout)
template<int K, int MTOT, int EPI>
__global__ __launch_bounds__(256, 2)
void spmm_kernel(const float* __restrict__ WT, const uint32_t* __restrict__ min_,
                 const float* __restrict__ p1, const float* __restrict__ p2,
                 const float* __restrict__ p3, const float* __restrict__ p4,
                 const float* __restrict__ p5, const float* __restrict__ p6,
                 uint32_t* __restrict__ mq_, uint32_t* __restrict__ mk_,
                 uint32_t* __restrict__ mv_,
                 const float* __restrict__ res, float* __restrict__ fout,
                 float* __restrict__ vout, int write_v)
{
    __shared__ float Ws[128 * 64];
    int cb = blockIdx.x, mb = blockIdx.y;
    int tid = threadIdx.x, wid = tid >> 5, lane = tid & 31;
    int m0 = mb * 64;

    float2 acc[8][4];
#pragma unroll
    for (int j = 0; j < 8; j++)
#pragma unroll
        for (int t = 0; t < 4; t++) acc[j][t] = make_float2(0.f, 0.f);

    const float* Wl = Ws + 2 * lane;
    int r0 = tid >> 4;
    int mm = (tid & 15) * 4;
    const int NW = K / 32;

#pragma unroll 1
    for (int kt = 0; kt < K / 128; kt++) {
        // stage 128 x 64 weight tile
        const float* src = WT + (size_t)(kt * 128 + r0) * MTOT + m0 + mm;
#pragma unroll
        for (int r = 0; r < 8; r++)
            *(float4*)&Ws[(r0 + 16 * r) * 64 + mm] = *(const float4*)(src + (size_t)16 * r * MTOT);
        __syncthreads();

#pragma unroll
        for (int j = 0; j < 8; j++) {
            int col = cb * 64 + wid * 8 + j;
            const uint32_t* mp = min_ + (size_t)col * 4 * NW + kt * 4;
#pragma unroll
            for (int t = 0; t < 4; t++) {
                uint4 mw = *(const uint4*)(mp + (size_t)t * NW);
                uint32_t w;
                w = mw.x;
                while (w) { int bi = __ffs(w) - 1; w &= w - 1;
                    float2 u = *(const float2*)(Wl + bi * 64);
                    acc[j][t].x += u.x; acc[j][t].y += u.y; }
                w = mw.y;
                while (w) { int bi = __ffs(w) - 1; w &= w - 1;
                    float2 u = *(const float2*)(Wl + (32 + bi) * 64);
                    acc[j][t].x += u.x; acc[j][t].y += u.y; }
                w = mw.z;
                while (w) { int bi = __ffs(w) - 1; w &= w - 1;
                    float2 u = *(const float2*)(Wl + (64 + bi) * 64);
                    acc[j][t].x += u.x; acc[j][t].y += u.y; }
                w = mw.w;
                while (w) { int bi = __ffs(w) - 1; w &= w - 1;
                    float2 u = *(const float2*)(Wl + (96 + bi) * 64);
                    acc[j][t].x += u.x; acc[j][t].y += u.y; }
            }
        }
        __syncthreads();
    }

    // ---------------- epilogue ----------------
    if (EPI == 0) {
        int part = mb >> 3;                 // 0:q 1:k 2:v
        int c0 = ((mb & 7) << 6) + 2 * lane;
        const float* sp = (part == 0) ? p1 : (part == 1) ? p3 : p5;
        const float* bp = (part == 0) ? p2 : (part == 1) ? p4 : p6;
        uint32_t* mo = (part == 0) ? mq_ : (part == 1) ? mk_ : mv_;
        float s0v = sp[c0], s1v = sp[c0 + 1], b0v = bp[c0], b1v = bp[c0 + 1];
#pragma unroll
        for (int j = 0; j < 8; j++) {
            int col = cb * 64 + wid * 8 + j;
            int b_ = col >> 10, v_ = col & 1023;
            float m0f = 0.f, m1f = 0.f;
#pragma unroll
            for (int t = 0; t < 4; t++) {
                float pa = acc[j][t].x * s0v + b0v;
                float pb = acc[j][t].y * s1v + b1v;
                float h0 = m0f + (pa - m0f) * 0.5f; uint32_t ss0 = (h0 >= 1.f); m0f = ss0 ? 0.f : h0;
                float h1 = m1f + (pb - m1f) * 0.5f; uint32_t ss1 = (h1 >= 1.f); m1f = ss1 ? 0.f : h1;
                put_word2(ss0 | (ss1 << 1), lane, mo + ((size_t)col * 4 + t) * 16 + 2 * (mb & 7));
                if (part == 2 && write_v) {
                    int tb = t * 8 + b_;
                    float2 f = make_float2(ss0 ? 1.f : 0.f, ss1 ? 1.f : 0.f);
                    *(float2*)(vout + ((size_t)(tb * 8 + (mb - 16)) * 1024 + v_) * 64 + 2 * lane) = f;
                }
            }
        }
    } else if (EPI == 1 || EPI == 2) {
        int c0 = (mb << 6) + 2 * lane;
        float cb0 = p1[c0], cb1 = p1[c0 + 1];
        float s0v = p2[c0], s1v = p2[c0 + 1];
        float b0v = p3[c0], b1v = p3[c0 + 1];
        const int WOUT = (EPI == 1) ? 16 : 64;
#pragma unroll
        for (int j = 0; j < 8; j++) {
            int col = cb * 64 + wid * 8 + j;
            int b_ = col >> 10, v_ = col & 1023;
            float m0f = 0.f, m1f = 0.f;
#pragma unroll
            for (int t = 0; t < 4; t++) {
                float pa = (acc[j][t].x + cb0) * s0v + b0v;
                float pb = (acc[j][t].y + cb1) * s1v + b1v;
                if (EPI == 1) {
                    size_t adr = ((size_t)((t * 8 + b_) * 1024 + v_)) * 512 + c0;
                    float2 rx = *(const float2*)(res + adr);
                    pa += rx.x; pb += rx.y;
                    *(float2*)(fout + adr) = make_float2(pa, pb);
                }
                float h0 = m0f + (pa - m0f) * 0.5f; uint32_t ss0 = (h0 >= 1.f); m0f = ss0 ? 0.f : h0;
                float h1 = m1f + (pb - m1f) * 0.5f; uint32_t ss1 = (h1 >= 1.f); m1f = ss1 ? 0.f : h1;
                put_word2(ss0 | (ss1 << 1), lane, mq_ + ((size_t)col * 4 + t) * WOUT + 2 * mb);
            }
        }
    } else {   // EPI == 3: fc2 + residual -> floats
        int c0 = (mb << 6) + 2 * lane;
        float cb0 = p1[c0], cb1 = p1[c0 + 1];
        float s0v = p2[c0], s1v = p2[c0 + 1];
        float b0v = p3[c0], b1v = p3[c0 + 1];
#pragma unroll
        for (int j = 0; j < 8; j++) {
            int col = cb * 64 + wid * 8 + j;
            int b_ = col >> 10, v_ = col & 1023;
#pragma unroll
            for (int t = 0; t < 4; t++) {
                size_t adr = ((size_t)((t * 8 + b_) * 1024 + v_)) * 512 + c0;
                float2 rx = *(const float2*)(res + adr);
                float pa = (acc[j][t].x + cb0) * s0v + b0v + rx.x;
                float pb = (acc[j][t].y + cb1) * s1v + b1v + rx.y;
                *(float2*)(fout + adr) = make_float2(pa, pb);
            }
        }
    }
}

// ---------------- attn phase 1: attn[d][e] = popc sum over 2048 l ----------------
__global__ __launch_bounds__(256)
void attn1_kernel(const uint32_t* __restrict__ mkb, const uint32_t* __restrict__ mv,
                  float* __restrict__ attn)
{
    int idx = blockIdx.x;
    int h = idx & 7, b = (idx >> 3) & 7, n_ = idx >> 6;
    __shared__ uint32_t Kw[64][65];
    __shared__ uint32_t Vw[64][65];
    int tid = threadIdx.x, wid = tid >> 5, lane = tid & 31;

    for (int chunk = wid; chunk < 64; chunk += 8) {
        int t = (n_ << 1) + (chunk >> 5);
        int nn = (chunk & 31) * 32 + lane;
        size_t cbase = ((size_t)(b * 1024 + nn) * 4 + t) * 16;
        uint32_t k0 = mkb[cbase + 2 * h], k1 = mkb[cbase + 2 * h + 1];
        uint32_t v0 = mv[cbase + 2 * h],  v1 = mv[cbase + 2 * h + 1];
#pragma unroll
        for (int d = 0; d < 32; d++) {
            uint32_t bk = __ballot_sync(0xffffffffu, (k0 >> d) & 1);
            uint32_t bv = __ballot_sync(0xffffffffu, (v0 >> d) & 1);
            if (lane == 0) { Kw[d][chunk] = bk; Vw[d][chunk] = bv; }
        }
#pragma unroll
        for (int d = 0; d < 32; d++) {
            uint32_t bk = __ballot_sync(0xffffffffu, (k1 >> d) & 1);
            uint32_t bv = __ballot_sync(0xffffffffu, (v1 >> d) & 1);
            if (lane == 0) { Kw[32 + d][chunk] = bk; Vw[32 + d][chunk] = bv; }
        }
    }
    __syncthreads();

    int d = tid >> 2, eg = tid & 3;
    int acc[16];
#pragma unroll
    for (int j = 0; j < 16; j++) acc[j] = 0;
#pragma unroll 4
    for (int w = 0; w < 64; w++) {
        uint32_t kw = Kw[d][w];
#pragma unroll
        for (int j = 0; j < 16; j++)
            acc[j] += __popc(kw & Vw[eg + 4 * j][w]);
    }
    float* dst = attn + (size_t)idx * 4096 + d * 64 + eg;
#pragma unroll
    for (int j = 0; j < 16; j++)
        dst[4 * j] = (float)acc[j] * (1.0f / 1024.0f);
}

// ---------------- attn phase 2: out[l][e] = sum_{d: Q[l,d]=1} attn[d][e] ----------------
__global__ __launch_bounds__(256)
void attn2_kernel(const uint32_t* __restrict__ mq, const float* __restrict__ attn,
                  float* __restrict__ yT)
{
    int idx = blockIdx.y, lt = blockIdx.x;
    int h = idx & 7, b = (idx >> 3) & 7, n_ = idx >> 6;
    int t = (n_ << 1) + (lt >> 4);
    int nn0 = (lt & 15) << 6;

    __shared__ float Atn[64 * 65];
    int tid = threadIdx.x;
    const float* src = attn + (size_t)idx * 4096;
    for (int i = tid; i < 4096; i += 256)
        Atn[(i >> 6) * 65 + (i & 63)] = src[i];
    __syncthreads();

    int l = tid >> 2, e0 = (tid & 3) << 4;
    int vv = nn0 + l;
    size_t mi = ((size_t)(b * 1024 + vv) * 4 + t) * 16 + 2 * h;
    uint32_t q0 = mq[mi], q1 = mq[mi + 1];
    float acc[16];
#pragma unroll
    for (int j = 0; j < 16; j++) acc[j] = 0.f;
    while (q0) {
        int d = __ffs(q0) - 1; q0 &= q0 - 1;
        const float* a = Atn + d * 65 + e0;
#pragma unroll
        for (int j = 0; j < 16; j++) acc[j] += a[j];
    }
    while (q1) {
        int d = __ffs(q1) - 1 + 32; q1 &= q1 - 1;
        const float* a = Atn + d * 65 + e0;
#pragma unroll
        for (int j = 0; j < 16; j++) acc[j] += a[j];
    }
    float* dst = yT + ((size_t)((t * 8 + b) * 1024 + vv)) * 512 + h * 64 + e0;
#pragma unroll
    for (int j = 0; j < 16; j += 4)
        *(float4*)(dst + j) = make_float4(acc[j], acc[j + 1], acc[j + 2], acc[j + 3]);
}

// ---------------- host launcher ----------------
extern "C" void kernel_launch(void* const* d_in, const int* in_sizes, int n_in,
                              void* d_out, int out_size)
{
    const float* x    = (const float*)d_in[0];
    const float* qw   = (const float*)d_in[1];
    const float* qs   = (const float*)d_in[2];
    const float* qb   = (const float*)d_in[3];
    const float* kw   = (const float*)d_in[4];
    const float* ks_  = (const float*)d_in[5];
    const float* kb   = (const float*)d_in[6];
    const float* vw   = (const float*)d_in[7];
    const float* vs   = (const float*)d_in[8];
    const float* vb   = (const float*)d_in[9];
    const float* pw   = (const float*)d_in[10];
    const float* pwb  = (const float*)d_in[11];
    const float* ps   = (const float*)d_in[12];
    const float* psb  = (const float*)d_in[13];
    const float* f1w  = (const float*)d_in[14];
    const float* f1b  = (const float*)d_in[15];
    const float* f1s  = (const float*)d_in[16];
    const float* f1sb = (const float*)d_in[17];
    const float* f2w  = (const float*)d_in[18];
    const float* f2b  = (const float*)d_in[19];
    const float* f2s  = (const float*)d_in[20];
    const float* f2sb = (const float*)d_in[21];

    float *xt, *yb, *xattn, *f2o, *wqkv, *wp, *wf1, *wf2, *attn;
    uint32_t *mx, *mq, *mkb, *mv, *mpr, *mm1, *mh;
    cudaGetSymbolAddress((void**)&xt,    g_xt);
    cudaGetSymbolAddress((void**)&yb,    g_y);
    cudaGetSymbolAddress((void**)&xattn, g_xattn);
    cudaGetSymbolAddress((void**)&f2o,   g_f2);
    cudaGetSymbolAddress((void**)&wqkv,  g_wqkv);
    cudaGetSymbolAddress((void**)&wp,    g_wp);
    cudaGetSymbolAddress((void**)&wf1,   g_wf1);
    cudaGetSymbolAddress((void**)&wf2,   g_wf2);
    cudaGetSymbolAddress((void**)&attn,  g_attn);
    cudaGetSymbolAddress((void**)&mx,    g_mx);
    cudaGetSymbolAddress((void**)&mq,    g_mq);
    cudaGetSymbolAddress((void**)&mkb,   g_mk);
    cudaGetSymbolAddress((void**)&mv,    g_mv);
    cudaGetSymbolAddress((void**)&mpr,   g_mpr);
    cudaGetSymbolAddress((void**)&mm1,   g_mm1);
    cudaGetSymbolAddress((void**)&mh,    g_mh);

    float* out = (float*)d_out;
    int write_v = (out_size >= 2 * MAIN_ELEMS);
    float* vout = write_v ? (out + MAIN_ELEMS) : f2o;

    dim3 tb32(32, 8);
    qkvw_kern<<<dim3(CC / 32, CC / 32, 3), tb32>>>(qw, kw, vw, wqkv);
    tkern<<<dim3(CC / 32, CC / 32, 1), tb32>>>(pw,  wp,  CC,  CC);
    tkern<<<dim3(CC / 32, HID / 32, 1), tb32>>>(f1w, wf1, HID, CC);
    tkern<<<dim3(HID / 32, CC / 32, 1), tb32>>>(f2w, wf2, CC,  HID);

    // x -> [tb][v][c]
    tkern<<<dim3(VV / 32, CC / 32, NTB), tb32>>>(x, xt, CC, VV);

    // shortcut LIF -> x masks
    lif2mask<<<NBV, 256>>>(xt, mx, 1.0f);

    // qkv staged sparse GEMM + BN + LIF -> q/k/v masks (+ v float output)
    spmm_kernel<512, 1536, 0><<<dim3(128, 24), 256>>>(
        wqkv, mx, qs, qb, ks_, kb, vs, vb, mq, mkb, mv, nullptr, nullptr, vout, write_v);

    // bit-domain attention
    attn1_kernel<<<128, 256>>>(mkb, mv, attn);
    attn2_kernel<<<dim3(32, 128), 256>>>(mq, attn, yb);

    // attn LIF (vth=0.5) -> proj input masks
    lif2mask<<<NBV, 256>>>(yb, mpr, 0.5f);

    // proj + BN + residual(xt) -> xattn floats + MLP input masks
    spmm_kernel<512, 512, 1><<<dim3(128, 8), 256>>>(
        wp, mpr, pwb, ps, psb, nullptr, nullptr, nullptr, mm1, nullptr, nullptr,
        xt, xattn, nullptr, 0);

    // fc1 + BN + LIF -> hidden masks
    spmm_kernel<512, 2048, 2><<<dim3(128, 32), 256>>>(
        wf1, mm1, f1b, f1s, f1sb, nullptr, nullptr, nullptr, mh, nullptr, nullptr,
        nullptr, nullptr, nullptr, 0);

    // fc2 + BN + residual(xattn) -> f2o floats
    spmm_kernel<2048, 512, 3><<<dim3(128, 8), 256>>>(
        wf2, mh, f2b, f2s, f2sb, nullptr, nullptr, nullptr, nullptr, nullptr, nullptr,
        xattn, f2o, nullptr, 0);

    // main output: transpose back to (T,B,C,V)
    tkern<<<dim3(CC / 32, VV / 32, NTB), tb32>>>(f2o, out, VV, CC);
}